// round 10
// baseline (speedup 1.0000x reference)
#include <cuda_runtime.h>
#include <cuda_bf16.h>
#include <cstdint>

// Loss_Labels: -mean over B of ( label==1 ? log_softmax(s,a)[0]
//                              : label==2 ? log_softmax(s,a)[1] : 0 )
//
// Labels int32 on device. 12 B/element, ~100 MB streamed.
// R10 = R9 (pair body, occ 8, one wave) + balanced work split:
//   phase 1: every thread does EXACTLY p = nvec/(2S) pair-iterations
//            (uniform, 6 front-batched 128-bit loads each)
//   phase 2: remaining vecs via single-float4 grid-stride (<=1 iter/thread,
//            4-element quantum -> ~1% residual imbalance vs 15.6% in R9)
// Fused last-block finalize, deterministic fixed-order sums.

#define NSM 148
#define OCC 8
#define NB (NSM * OCC)   // 1184 blocks: one full wave at 8 blocks/SM
#define NT 256

__device__ float g_partials[NB];
__device__ unsigned int g_done_count;   // zero-init; reset by last block

__device__ __forceinline__ float err_term(float s, float a, int lab) {
    // d = a - s; lse - s = max(d,0) + log(1 + exp(-|d|))  (arg in (1,2])
    float d = a - s;
    float t = fmaxf(d, 0.0f) + __logf(1.0f + __expf(-fabsf(d)));
    return (lab == 1) ? -t : ((lab == 2) ? (d - t) : 0.0f);
}

__global__ void __launch_bounds__(NT, OCC)
loss_fused_kernel(const float4* __restrict__ s4,
                  const float4* __restrict__ a4,
                  const int4*   __restrict__ l4,
                  float* __restrict__ out,
                  int n, int nvec)
{
    const int S   = gridDim.x * blockDim.x;          // total threads
    const int tid = blockIdx.x * blockDim.x + threadIdx.x;
    const int p   = nvec / (2 * S);                  // full pair-iters per thread

    float acc = 0.0f;

    // Phase 1: exactly p pair-iterations per thread (perfectly balanced).
#pragma unroll 1
    for (int k = 0; k < p; k++) {
        int i = tid + k * S;                         // pair index
        float4 s0 = s4[2 * i];
        float4 s1 = s4[2 * i + 1];
        float4 a0 = a4[2 * i];
        float4 a1 = a4[2 * i + 1];
        int4   l0 = l4[2 * i];
        int4   l1 = l4[2 * i + 1];

        acc += err_term(s0.x, a0.x, l0.x);
        acc += err_term(s0.y, a0.y, l0.y);
        acc += err_term(s0.z, a0.z, l0.z);
        acc += err_term(s0.w, a0.w, l0.w);
        acc += err_term(s1.x, a1.x, l1.x);
        acc += err_term(s1.y, a1.y, l1.y);
        acc += err_term(s1.z, a1.z, l1.z);
        acc += err_term(s1.w, a1.w, l1.w);
    }

    // Phase 2: remaining float4s [2*S*p, nvec), single-vec grid-stride
    // (at most one iteration per thread for our shapes).
#pragma unroll 1
    for (int i = 2 * S * p + tid; i < nvec; i += S) {
        float4 s = s4[i];
        float4 a = a4[i];
        int4   l = l4[i];
        acc += err_term(s.x, a.x, l.x);
        acc += err_term(s.y, a.y, l.y);
        acc += err_term(s.z, a.z, l.z);
        acc += err_term(s.w, a.w, l.w);
    }

    // scalar tail (n % 4 != 0); n = 8388608 divisible, kept for safety
    if (blockIdx.x == 0) {
        const float* s = (const float*)s4;
        const float* a = (const float*)a4;
        const int*   l = (const int*)l4;
        for (int t = nvec * 4 + threadIdx.x; t < n; t += NT)
            acc += err_term(s[t], a[t], l[t]);
    }

    // deterministic block tree reduction
    __shared__ float sm[NT];
    sm[threadIdx.x] = acc;
    __syncthreads();
#pragma unroll
    for (int off = NT / 2; off > 0; off >>= 1) {
        if (threadIdx.x < off) sm[threadIdx.x] += sm[threadIdx.x + off];
        __syncthreads();
    }

    __shared__ bool s_last;
    if (threadIdx.x == 0) {
        g_partials[blockIdx.x] = sm[0];
        __threadfence();
        unsigned int prev = atomicAdd(&g_done_count, 1u);
        s_last = (prev == (unsigned int)(gridDim.x - 1));
    }
    __syncthreads();

    if (s_last) {
        __threadfence();  // all partials visible
        float facc = 0.0f;
        for (int k = threadIdx.x; k < NB; k += NT)
            facc += g_partials[k];
        sm[threadIdx.x] = facc;
        __syncthreads();
#pragma unroll
        for (int off = NT / 2; off > 0; off >>= 1) {
            if (threadIdx.x < off) sm[threadIdx.x] += sm[threadIdx.x + off];
            __syncthreads();
        }
        if (threadIdx.x == 0) {
            out[0] = -sm[0] / (float)n;
            g_done_count = 0;   // reset for next graph replay
        }
    }
}

extern "C" void kernel_launch(void* const* d_in, const int* in_sizes, int n_in,
                              void* d_out, int out_size)
{
    const float* s   = (const float*)d_in[0];  // synonymy_score [B]
    const float* a   = (const float*)d_in[1];  // antonymy_score [B]
    const int*   lab = (const int*)d_in[2];    // labels [B] (int32 on device)
    float*       out = (float*)d_out;

    const int n    = in_sizes[0];
    const int nvec = n / 4;

    loss_fused_kernel<<<NB, NT>>>((const float4*)s, (const float4*)a,
                                  (const int4*)lab, out, n, nvec);
}

// round 12
// speedup vs baseline: 1.0169x; 1.0169x over previous
#include <cuda_runtime.h>
#include <cuda_bf16.h>
#include <cstdint>

// Loss_Labels: -mean over B of ( label==1 ? log_softmax(s,a)[0]
//                              : label==2 ? log_softmax(s,a)[1] : 0 )
//
// Labels int32 on device. 12 B/element, ~100 MB streamed.
// R12 = R11 (R9 pair streaming body + hierarchical finalize) with the root
// reduction FIXED: NGROUP=37 > 32 lanes, so each lane now sums g_gsum[lane]
// and g_gsum[lane+32] (fixed order -> deterministic). R11 dropped groups
// 32..36 (5/37 = 13.5% of data = the observed rel_err).

#define NSM 148
#define OCC 8
#define NB (NSM * OCC)       // 1184 blocks
#define NT 256
#define GSIZE 32             // blocks per group
#define NGROUP (NB / GSIZE)  // 37
#define CSTRIDE 64           // 64 uints = 256 B between group counters

__device__ float g_partials[NB];
__device__ float g_gsum[NGROUP];
__device__ unsigned int g_gcount[NGROUP * CSTRIDE];  // strided counters
__device__ unsigned int g_rootcount;

__device__ __forceinline__ float err_term(float s, float a, int lab) {
    // d = a - s; lse - s = max(d,0) + log(1 + exp(-|d|))  (arg in (1,2])
    float d = a - s;
    float t = fmaxf(d, 0.0f) + __logf(1.0f + __expf(-fabsf(d)));
    return (lab == 1) ? -t : ((lab == 2) ? (d - t) : 0.0f);
}

__global__ void __launch_bounds__(NT, OCC)
loss_fused_kernel(const float4* __restrict__ s4,
                  const float4* __restrict__ a4,
                  const int4*   __restrict__ l4,
                  float* __restrict__ out,
                  int n, int nvec)
{
    const int npair  = nvec / 2;
    const int stride = gridDim.x * blockDim.x;

    float acc = 0.0f;
    for (int i = blockIdx.x * blockDim.x + threadIdx.x; i < npair; i += stride) {
        // 6 independent 128-bit loads, front-batched
        float4 s0 = s4[2 * i];
        float4 s1 = s4[2 * i + 1];
        float4 a0 = a4[2 * i];
        float4 a1 = a4[2 * i + 1];
        int4   l0 = l4[2 * i];
        int4   l1 = l4[2 * i + 1];

        acc += err_term(s0.x, a0.x, l0.x);
        acc += err_term(s0.y, a0.y, l0.y);
        acc += err_term(s0.z, a0.z, l0.z);
        acc += err_term(s0.w, a0.w, l0.w);
        acc += err_term(s1.x, a1.x, l1.x);
        acc += err_term(s1.y, a1.y, l1.y);
        acc += err_term(s1.z, a1.z, l1.z);
        acc += err_term(s1.w, a1.w, l1.w);
    }

    // scalar tail: [npair*8, n) (empty for n = 8388608; kept for safety)
    if (blockIdx.x == 0) {
        const float* s = (const float*)s4;
        const float* a = (const float*)a4;
        const int*   l = (const int*)l4;
        for (int t = npair * 8 + threadIdx.x; t < n; t += NT)
            acc += err_term(s[t], a[t], l[t]);
    }

    // deterministic block tree reduction
    __shared__ float sm[NT];
    sm[threadIdx.x] = acc;
    __syncthreads();
#pragma unroll
    for (int off = NT / 2; off > 0; off >>= 1) {
        if (threadIdx.x < off) sm[threadIdx.x] += sm[threadIdx.x + off];
        __syncthreads();
    }

    const int grp = blockIdx.x >> 5;           // group id (32 blocks/group)
    __shared__ bool s_glast;
    if (threadIdx.x == 0) {
        g_partials[blockIdx.x] = sm[0];
        __threadfence();
        unsigned int prev = atomicAdd(&g_gcount[grp * CSTRIDE], 1u);
        s_glast = (prev == GSIZE - 1);
    }
    __syncthreads();

    if (s_glast) {
        const int lane = threadIdx.x & 31;
        __shared__ bool s_rlast;
        if (threadIdx.x < 32) {
            // warp 0: one parallel L2 round over the group's 32 partials,
            // fixed-order shuffle reduce (deterministic).
            __threadfence();
            float v = g_partials[grp * GSIZE + lane];
#pragma unroll
            for (int off = 16; off > 0; off >>= 1)
                v += __shfl_down_sync(0xffffffffu, v, off);
            if (lane == 0) {
                g_gsum[grp] = v;
                __threadfence();
                unsigned int prev2 = atomicAdd(&g_rootcount, 1u);
                s_rlast = (prev2 == NGROUP - 1);
            }
        }
        __syncthreads();

        if (s_rlast && threadIdx.x < 32) {
            __threadfence();
            // NGROUP = 37 > 32 lanes: each lane covers lane and lane+32.
            float v = (lane < NGROUP) ? g_gsum[lane] : 0.0f;
            if (lane + 32 < NGROUP) v += g_gsum[lane + 32];
#pragma unroll
            for (int off = 16; off > 0; off >>= 1)
                v += __shfl_down_sync(0xffffffffu, v, off);
            if (lane == 0) {
                out[0] = -v / (float)n;
                g_rootcount = 0;                     // reset for next replay
            }
            // reset group counters (lanes cover all 37 groups)
            if (lane < NGROUP) g_gcount[lane * CSTRIDE] = 0;
            if (lane + 32 < NGROUP) g_gcount[(lane + 32) * CSTRIDE] = 0;
        }
    }
}

extern "C" void kernel_launch(void* const* d_in, const int* in_sizes, int n_in,
                              void* d_out, int out_size)
{
    const float* s   = (const float*)d_in[0];  // synonymy_score [B]
    const float* a   = (const float*)d_in[1];  // antonymy_score [B]
    const int*   lab = (const int*)d_in[2];    // labels [B] (int32 on device)
    float*       out = (float*)d_out;

    const int n    = in_sizes[0];
    const int nvec = n / 4;

    loss_fused_kernel<<<NB, NT>>>((const float4*)s, (const float4*)a,
                                  (const int4*)lab, out, n, nvec);
}

// round 13
// speedup vs baseline: 1.0381x; 1.0208x over previous
#include <cuda_runtime.h>
#include <cuda_bf16.h>
#include <cstdint>

// Loss_Labels: -mean over B of ( label==1 ? log_softmax(s,a)[0]
//                              : label==2 ? log_softmax(s,a)[1] : 0 )
//
// Labels int32 on device. 12 B/element, ~100 MB streamed.
// R13 = R9 pair streaming body (6 front-batched 128-bit loads) + flat
// last-block finalize (R12's hierarchy was slower), with ONE change:
// NT 256 -> 512, OCC 8 -> 4 (grid 592 = one wave, same 2048 thr/SM).
// Halves partial count + finalize read phase + arrival count.

#define NSM 148
#define OCC 4
#define NB (NSM * OCC)   // 592 blocks: one full wave at 4 blocks/SM
#define NT 512

__device__ float g_partials[NB];
__device__ unsigned int g_done_count;   // zero-init; reset by last block

__device__ __forceinline__ float err_term(float s, float a, int lab) {
    // d = a - s; lse - s = max(d,0) + log(1 + exp(-|d|))  (arg in (1,2])
    float d = a - s;
    float t = fmaxf(d, 0.0f) + __logf(1.0f + __expf(-fabsf(d)));
    return (lab == 1) ? -t : ((lab == 2) ? (d - t) : 0.0f);
}

__global__ void __launch_bounds__(NT, OCC)
loss_fused_kernel(const float4* __restrict__ s4,
                  const float4* __restrict__ a4,
                  const int4*   __restrict__ l4,
                  float* __restrict__ out,
                  int n, int nvec)
{
    const int npair  = nvec / 2;               // pairs of float4
    const int stride = gridDim.x * blockDim.x;

    float acc = 0.0f;
    for (int i = blockIdx.x * blockDim.x + threadIdx.x; i < npair; i += stride) {
        // 6 independent 128-bit loads, front-batched
        float4 s0 = s4[2 * i];
        float4 s1 = s4[2 * i + 1];
        float4 a0 = a4[2 * i];
        float4 a1 = a4[2 * i + 1];
        int4   l0 = l4[2 * i];
        int4   l1 = l4[2 * i + 1];

        acc += err_term(s0.x, a0.x, l0.x);
        acc += err_term(s0.y, a0.y, l0.y);
        acc += err_term(s0.z, a0.z, l0.z);
        acc += err_term(s0.w, a0.w, l0.w);
        acc += err_term(s1.x, a1.x, l1.x);
        acc += err_term(s1.y, a1.y, l1.y);
        acc += err_term(s1.z, a1.z, l1.z);
        acc += err_term(s1.w, a1.w, l1.w);
    }

    // scalar tail: [npair*8, n) (empty for n = 8388608; kept for safety)
    if (blockIdx.x == 0) {
        const float* s = (const float*)s4;
        const float* a = (const float*)a4;
        const int*   l = (const int*)l4;
        for (int t = npair * 8 + threadIdx.x; t < n; t += NT)
            acc += err_term(s[t], a[t], l[t]);
    }

    // deterministic block tree reduction
    __shared__ float sm[NT];
    sm[threadIdx.x] = acc;
    __syncthreads();
#pragma unroll
    for (int off = NT / 2; off > 0; off >>= 1) {
        if (threadIdx.x < off) sm[threadIdx.x] += sm[threadIdx.x + off];
        __syncthreads();
    }

    __shared__ bool s_last;
    if (threadIdx.x == 0) {
        g_partials[blockIdx.x] = sm[0];
        __threadfence();
        unsigned int prev = atomicAdd(&g_done_count, 1u);
        s_last = (prev == (unsigned int)(gridDim.x - 1));
    }
    __syncthreads();

    if (s_last) {
        __threadfence();  // all partials visible
        float facc = 0.0f;
        for (int k = threadIdx.x; k < NB; k += NT)
            facc += g_partials[k];
        sm[threadIdx.x] = facc;
        __syncthreads();
#pragma unroll
        for (int off = NT / 2; off > 0; off >>= 1) {
            if (threadIdx.x < off) sm[threadIdx.x] += sm[threadIdx.x + off];
            __syncthreads();
        }
        if (threadIdx.x == 0) {
            out[0] = -sm[0] / (float)n;
            g_done_count = 0;   // reset for next graph replay
        }
    }
}

extern "C" void kernel_launch(void* const* d_in, const int* in_sizes, int n_in,
                              void* d_out, int out_size)
{
    const float* s   = (const float*)d_in[0];  // synonymy_score [B]
    const float* a   = (const float*)d_in[1];  // antonymy_score [B]
    const int*   lab = (const int*)d_in[2];    // labels [B] (int32 on device)
    float*       out = (float*)d_out;

    const int n    = in_sizes[0];
    const int nvec = n / 4;

    loss_fused_kernel<<<NB, NT>>>((const float4*)s, (const float4*)a,
                                  (const int4*)lab, out, n, nvec);
}

// round 14
// speedup vs baseline: 1.1364x; 1.0947x over previous
#include <cuda_runtime.h>
#include <cuda_bf16.h>
#include <cstdint>

// Loss_Labels: -mean over B of ( label==1 ? log_softmax(s,a)[0]
//                              : label==2 ? log_softmax(s,a)[1] : 0 )
//
// Labels int32 on device. 12 B/element, ~100 MB streamed.
// R14 = R9 (champion: pair body w/ 6 front-batched 128-bit loads, NT=256,
// OCC=8, grid 1184 = one wave, flat last-block finalize) with ONE tweak:
// the finalize reads g_partials as float4 (296 vec loads, 2 rounds) instead
// of 1184 scalar loads (5 rounds). Fixed-order sums -> deterministic.

#define NSM 148
#define OCC 8
#define NB (NSM * OCC)   // 1184 blocks: one full wave at 8 blocks/SM
#define NT 256

__device__ float g_partials[NB];
__device__ unsigned int g_done_count;   // zero-init; reset by last block

__device__ __forceinline__ float err_term(float s, float a, int lab) {
    // d = a - s; lse - s = max(d,0) + log(1 + exp(-|d|))  (arg in (1,2])
    float d = a - s;
    float t = fmaxf(d, 0.0f) + __logf(1.0f + __expf(-fabsf(d)));
    return (lab == 1) ? -t : ((lab == 2) ? (d - t) : 0.0f);
}

__global__ void __launch_bounds__(NT, OCC)
loss_fused_kernel(const float4* __restrict__ s4,
                  const float4* __restrict__ a4,
                  const int4*   __restrict__ l4,
                  float* __restrict__ out,
                  int n, int nvec)
{
    const int npair  = nvec / 2;               // pairs of float4
    const int stride = gridDim.x * blockDim.x;

    float acc = 0.0f;
    for (int i = blockIdx.x * blockDim.x + threadIdx.x; i < npair; i += stride) {
        // 6 independent 128-bit loads, front-batched
        float4 s0 = s4[2 * i];
        float4 s1 = s4[2 * i + 1];
        float4 a0 = a4[2 * i];
        float4 a1 = a4[2 * i + 1];
        int4   l0 = l4[2 * i];
        int4   l1 = l4[2 * i + 1];

        acc += err_term(s0.x, a0.x, l0.x);
        acc += err_term(s0.y, a0.y, l0.y);
        acc += err_term(s0.z, a0.z, l0.z);
        acc += err_term(s0.w, a0.w, l0.w);
        acc += err_term(s1.x, a1.x, l1.x);
        acc += err_term(s1.y, a1.y, l1.y);
        acc += err_term(s1.z, a1.z, l1.z);
        acc += err_term(s1.w, a1.w, l1.w);
    }

    // scalar tail: [npair*8, n) (empty for n = 8388608; kept for safety)
    if (blockIdx.x == 0) {
        const float* s = (const float*)s4;
        const float* a = (const float*)a4;
        const int*   l = (const int*)l4;
        for (int t = npair * 8 + threadIdx.x; t < n; t += NT)
            acc += err_term(s[t], a[t], l[t]);
    }

    // deterministic block tree reduction
    __shared__ float sm[NT];
    sm[threadIdx.x] = acc;
    __syncthreads();
#pragma unroll
    for (int off = NT / 2; off > 0; off >>= 1) {
        if (threadIdx.x < off) sm[threadIdx.x] += sm[threadIdx.x + off];
        __syncthreads();
    }

    __shared__ bool s_last;
    if (threadIdx.x == 0) {
        g_partials[blockIdx.x] = sm[0];
        __threadfence();
        unsigned int prev = atomicAdd(&g_done_count, 1u);
        s_last = (prev == (unsigned int)(gridDim.x - 1));
    }
    __syncthreads();

    if (s_last) {
        __threadfence();  // all partials visible
        // vectorized partial read: NB/4 = 296 float4s over 256 threads
        float facc = 0.0f;
        const float4* p4 = (const float4*)g_partials;
#pragma unroll
        for (int k = threadIdx.x; k < NB / 4; k += NT) {
            float4 p = p4[k];
            facc += (p.x + p.y) + (p.z + p.w);
        }
        sm[threadIdx.x] = facc;
        __syncthreads();
#pragma unroll
        for (int off = NT / 2; off > 0; off >>= 1) {
            if (threadIdx.x < off) sm[threadIdx.x] += sm[threadIdx.x + off];
            __syncthreads();
        }
        if (threadIdx.x == 0) {
            out[0] = -sm[0] / (float)n;
            g_done_count = 0;   // reset for next graph replay
        }
    }
}

extern "C" void kernel_launch(void* const* d_in, const int* in_sizes, int n_in,
                              void* d_out, int out_size)
{
    const float* s   = (const float*)d_in[0];  // synonymy_score [B]
    const float* a   = (const float*)d_in[1];  // antonymy_score [B]
    const int*   lab = (const int*)d_in[2];    // labels [B] (int32 on device)
    float*       out = (float*)d_out;

    const int n    = in_sizes[0];
    const int nvec = n / 4;

    loss_fused_kernel<<<NB, NT>>>((const float4*)s, (const float4*)a,
                                  (const int4*)lab, out, n, nvec);
}